// round 16
// baseline (speedup 1.0000x reference)
#include <cuda_runtime.h>
#include <cuda_bf16.h>
#include <cstdint>
#include <cstddef>

// Fixed problem dims: B=4, S=2048 -> M=8192, K=4096, N=4096
#define KDIM 4096
#define NDIM 4096
#define MMAX 8192

#define BM 128
#define BN 64
#define BK 128
#define KT (KDIM / BK)      // 32 k-chunks (128B)
#define KI 18               // k-chunks done by IMMA warps
#define KD (KT - KI)        // 14 k-chunks -> dp4a as 28 chunks of 64B
#define ND64 (KD * 2)       // 28

#define TILES_TOT ((MMAX / BM) * (NDIM / BN))  // 64*64 = 4096
#define GRID 296                                // persistent CTAs (2/SM)

#define IMMA_STAGE (BM * BK + BN * BK)         // 24576 (A 16K + B 8K)
#define DP_STAGE   (BM * 64 + BN * 64)          // 12288 (A 8K + B 4K)
#define SM_DP   (3 * IMMA_STAGE)                // 73728 (IMMA: 3 buffers)
#define SM_PART (SM_DP + 2 * DP_STAGE)          // 98304
#define PART_STRIDE 68                          // padded int32 row stride (64 cols)
#define SMEM_TOTAL (SM_PART + 32 * PART_STRIDE * 4)  // 98304 + 8704 = 107008

// -------- device scratch --------
__device__ int8_t g_A8[(size_t)MMAX * KDIM];
__device__ int8_t g_B8[(size_t)NDIM * KDIM];
__device__ float  g_comb[KDIM];
__device__ float  g_sc[NDIM];

// -------- helpers --------
__device__ __forceinline__ uint32_t smem_u32(const void* p) {
    uint32_t a;
    asm("{ .reg .u64 t; cvta.to.shared.u64 t, %1; cvt.u32.u64 %0, t; }" : "=r"(a) : "l"(p));
    return a;
}
__device__ __forceinline__ void cp16(uint32_t s, const void* g) {
    asm volatile("cp.async.cg.shared.global [%0], [%1], 16;" :: "r"(s), "l"(g));
}
__device__ __forceinline__ void ldsm4(uint32_t* d, uint32_t addr) {
    asm volatile("ldmatrix.sync.aligned.m8n8.x4.shared.b16 {%0,%1,%2,%3}, [%4];"
                 : "=r"(d[0]), "=r"(d[1]), "=r"(d[2]), "=r"(d[3]) : "r"(addr));
}
__device__ __forceinline__ void imma(int* c, const uint32_t* a, const uint32_t* b) {
    asm volatile(
        "mma.sync.aligned.m16n8k32.row.col.s32.s8.s8.s32 "
        "{%0,%1,%2,%3}, {%4,%5,%6,%7}, {%8,%9}, {%0,%1,%2,%3};"
        : "+r"(c[0]), "+r"(c[1]), "+r"(c[2]), "+r"(c[3])
        : "r"(a[0]), "r"(a[1]), "r"(a[2]), "r"(a[3]), "r"(b[0]), "r"(b[1]));
}
__device__ __forceinline__ void dp4a_acc(int& c, uint32_t a, uint32_t b) {
    asm volatile("dp4a.s32.s32 %0, %1, %2, %0;" : "+r"(c) : "r"(a), "r"(b));
}
__device__ __forceinline__ void lds128(uint32_t* d, uint32_t addr) {
    asm volatile("ld.shared.v4.b32 {%0,%1,%2,%3}, [%4];"
                 : "=r"(d[0]), "=r"(d[1]), "=r"(d[2]), "=r"(d[3]) : "r"(addr));
}

// -------- preprocessing --------
__global__ void precomp_scales(const float* __restrict__ in_scale,
                               const float* __restrict__ act,
                               const float* __restrict__ w_scale) {
    int i = blockIdx.x * blockDim.x + threadIdx.x;
    float a = act[0];
    if (i < KDIM) g_comb[i] = __fdiv_rn(in_scale[i], a);
    if (i < NDIM) g_sc[i] = a * w_scale[i];
}

__global__ void quant_x(const float* __restrict__ x, int total4) {
    int i = blockIdx.x * blockDim.x + threadIdx.x;
    if (i >= total4) return;
    float4 v = reinterpret_cast<const float4*>(x)[i];
    int col = (i & (KDIM / 4 - 1)) * 4;
    int q0 = min(max(__float2int_rn(v.x * g_comb[col + 0]), -127), 127);
    int q1 = min(max(__float2int_rn(v.y * g_comb[col + 1]), -127), 127);
    int q2 = min(max(__float2int_rn(v.z * g_comb[col + 2]), -127), 127);
    int q3 = min(max(__float2int_rn(v.w * g_comb[col + 3]), -127), 127);
    uint32_t p = (uint32_t)(q0 & 0xFF) | ((uint32_t)(q1 & 0xFF) << 8) |
                 ((uint32_t)(q2 & 0xFF) << 16) | ((uint32_t)(q3 & 0xFF) << 24);
    reinterpret_cast<uint32_t*>(g_A8)[i] = p;
}

__global__ void conv_w(const int* __restrict__ w, int total4) {
    int i = blockIdx.x * blockDim.x + threadIdx.x;
    if (i >= total4) return;
    int4 v = reinterpret_cast<const int4*>(w)[i];
    uint32_t p = (uint32_t)(v.x & 0xFF) | ((uint32_t)(v.y & 0xFF) << 8) |
                 ((uint32_t)(v.z & 0xFF) << 16) | ((uint32_t)(v.w & 0xFF) << 24);
    reinterpret_cast<uint32_t*>(g_B8)[i] = p;
}

// -------- IMMA tile loader (A 128 rows, B 64 rows, XOR-swizzled, 128 threads) --------
__device__ __forceinline__ void load_imma(uint32_t sm, const char* gA, const char* gB,
                                          int kt, int t) {
    const char* ga = gA + (size_t)kt * BK;
    const char* gb = gB + (size_t)kt * BK;
#pragma unroll
    for (int i = 0; i < 8; i++) {
        int slot = t + i * 128;
        int row = slot >> 3, seg = slot & 7;
        cp16(sm + row * 128 + ((seg ^ (row & 7)) << 4),
             ga + (size_t)row * KDIM + seg * 16);
    }
#pragma unroll
    for (int i = 0; i < 4; i++) {
        int slot = t + i * 128;
        int row = slot >> 3, seg = slot & 7;
        cp16(sm + BM * 128 + row * 128 + ((seg ^ (row & 7)) << 4),
             gb + (size_t)row * KDIM + seg * 16);
    }
}

// -------- dp4a 64B-chunk loader: permuted 512B-window layout, 128 threads --------
// seg s of row r lives at (r>>3)*512 + (s*8 + (r&7))*16
__device__ __forceinline__ void load_dp(uint32_t sm, const char* gA, const char* gB,
                                        int koff, int t) {
#pragma unroll
    for (int i = 0; i < 4; i++) {
        int slot = t + i * 128;
        int row = slot >> 2, seg = slot & 3;
        uint32_t off = (uint32_t)(((row >> 3) << 9) + ((seg * 8 + (row & 7)) << 4));
        cp16(sm + off, gA + (size_t)row * KDIM + koff + seg * 16);
    }
#pragma unroll
    for (int i = 0; i < 2; i++) {
        int slot = t + i * 128;
        int row = slot >> 2, seg = slot & 3;
        uint32_t off = (uint32_t)(((row >> 3) << 9) + ((seg * 8 + (row & 7)) << 4));
        cp16(sm + 8192 + off, gB + (size_t)row * KDIM + koff + seg * 16);
    }
}

// ---- persistent 2-CTA hybrid GEMM: 256 thr/CTA, warps 4-7 IMMA, warps 0-3 dp4a ----
// Pipelines use the R10-proven race-free order: wait_group -> bar.sync -> issue -> compute
// (the barrier AFTER the wait guarantees ALL threads' cp.asyncs for the chunk landed).
// Handoff: single 32-row partial buffer, 4 strictly-alternating phases
// (ready: bar3, consumed: bar4, single pending set per barrier).
__global__ __launch_bounds__(256, 2)
void gemm_kernel(const float* __restrict__ bias, float* __restrict__ out) {
    extern __shared__ __align__(1024) char smem[];
    uint32_t sb = smem_u32(smem);
    int tid = threadIdx.x;
    int bid = blockIdx.x;
    int nt = (TILES_TOT - bid + GRID - 1) / GRID;   // tiles this CTA processes

    if (tid >= 128) {
        // ===== IMMA group (warps 4-7): 3-buffer per-chunk pipeline =====
        int it = tid - 128;
        int lane = it & 31, warp_m = it >> 5;        // 4 warps, warp tile 32x64 (all N)

        int tq = lane >> 3, r = lane & 7;
        int rowA[2], rowB[4];
#pragma unroll
        for (int im = 0; im < 2; im++) rowA[im] = warp_m * 32 + im * 16 + (tq & 1) * 8 + r;
        int segA = tq >> 1;
#pragma unroll
        for (int nb = 0; nb < 4; nb++) rowB[nb] = nb * 16 + (tq >> 1) * 8 + r;
        int segB = tq & 1;

        int pidx0 = warp_m * 8 + (lane >> 2);        // row within 32-row phase buffer
        int cl = (lane & 3) * 2;

        int ld_tile = bid, ld_kt = 0;
        const char* lA = (const char*)g_A8 + (size_t)(ld_tile >> 6) * BM * KDIM;
        const char* lB = (const char*)g_B8 + (size_t)(ld_tile & 63) * BN * KDIM;

        load_imma(sb + 0 * IMMA_STAGE, lA, lB, 0, it);
        asm volatile("cp.async.commit_group;" ::: "memory");
        ld_kt = 1;
        load_imma(sb + 1 * IMMA_STAGE, lA, lB, 1, it);
        asm volatile("cp.async.commit_group;" ::: "memory");

        int g = 0;   // global chunk counter; buffer = g % 3

#pragma unroll 1
        for (int t = 0; t < nt; t++) {
            int c[2][8][4];
#pragma unroll
            for (int im = 0; im < 2; im++)
#pragma unroll
                for (int n8 = 0; n8 < 8; n8++)
#pragma unroll
                    for (int q = 0; q < 4; q++) c[im][n8][q] = 0;

#pragma unroll 1
            for (int kt = 0; kt < KI; kt++) {
                asm volatile("cp.async.wait_group 1;" ::: "memory");  // own chunk g done
                asm volatile("bar.sync 1, 128;" ::: "memory");        // ALL chunk g done

                ld_kt++;
                if (ld_kt == KI) {
                    ld_kt = 0;
                    ld_tile += GRID;
                    if (ld_tile < TILES_TOT) {
                        lA = (const char*)g_A8 + (size_t)(ld_tile >> 6) * BM * KDIM;
                        lB = (const char*)g_B8 + (size_t)(ld_tile & 63) * BN * KDIM;
                    }
                }
                if (ld_tile < TILES_TOT)
                    load_imma(sb + (uint32_t)(((g + 2) % 3) * IMMA_STAGE), lA, lB, ld_kt, it);
                asm volatile("cp.async.commit_group;" ::: "memory");

                uint32_t sA = sb + (uint32_t)((g % 3) * IMMA_STAGE);
                uint32_t sB = sA + BM * 128;

#pragma unroll
                for (int j = 0; j < 4; j++) {
                    uint32_t a[2][4];
#pragma unroll
                    for (int im = 0; im < 2; im++) {
                        int seg = 2 * j + segA;
                        ldsm4(a[im], sA + rowA[im] * 128 + ((seg ^ (rowA[im] & 7)) << 4));
                    }
                    uint32_t bfr[8][2];
#pragma unroll
                    for (int nb = 0; nb < 4; nb++) {
                        uint32_t r4[4];
                        int seg = 2 * j + segB;
                        ldsm4(r4, sB + rowB[nb] * 128 + ((seg ^ (rowB[nb] & 7)) << 4));
                        bfr[2 * nb][0] = r4[0]; bfr[2 * nb][1] = r4[1];
                        bfr[2 * nb + 1][0] = r4[2]; bfr[2 * nb + 1][1] = r4[3];
                    }
#pragma unroll
                    for (int im = 0; im < 2; im++)
#pragma unroll
                        for (int n8 = 0; n8 < 8; n8++)
                            imma(c[im][n8], a[im], bfr[n8]);
                }
                g++;
            }

            // ---- 4-phase single-buffer dump (phase k = im*2 + half) ----
            int* part = (int*)(smem + SM_PART);
#pragma unroll
            for (int k = 0; k < 4; k++) {
                if (t > 0 || k > 0)
                    asm volatile("bar.sync 4, 256;" ::: "memory");  // phase k-1 consumed
                int im = k >> 1, half = k & 1;
#pragma unroll
                for (int n8 = 0; n8 < 8; n8++) {
                    int lc = cl + n8 * 8;
                    *reinterpret_cast<int2*>(&part[pidx0 * PART_STRIDE + lc]) =
                        make_int2(c[im][n8][half * 2], c[im][n8][half * 2 + 1]);
                }
                asm volatile("membar.cta;" ::: "memory");
                asm volatile("bar.arrive 3, 256;" ::: "memory");   // phase k ready
            }
        }
    } else {
        // ===== dp4a group (warps 0-3): 2-buffer 64B-chunk stream + phased merge =====
        int dt = tid;
        int dl = dt & 31, dwid = dt >> 5;
        int wm = dwid >> 1, wn = dwid & 1;   // 2x2 warps, warp tile 64x32
        int tm = dl >> 2, tn = dl & 3;       // 8x4 threads, thread tile 8x8

        uint32_t dbase = sb + SM_DP;

        uint32_t aBase = (uint32_t)(wm * 4096 + (tm << 4));
        uint32_t bOff[8];
#pragma unroll
        for (int j = 0; j < 8; j++) {
            int n = wn * 32 + tn + 4 * j;
            bOff[j] = (uint32_t)(((n >> 3) << 9) + ((n & 7) << 4));
        }

        int ld_tile = bid, ld_kt = 0;   // 64B-chunk index within tile
        const char* lA = (const char*)g_A8 + (size_t)(ld_tile >> 6) * BM * KDIM;
        const char* lB = (const char*)g_B8 + (size_t)(ld_tile & 63) * BN * KDIM;

        load_dp(dbase, lA, lB, KI * BK, dt);
        asm volatile("cp.async.commit_group;" ::: "memory");

        int g = 0;   // global 64B-chunk counter; buffer = g & 1

#pragma unroll 1
        for (int t = 0; t < nt; t++) {
            int T = bid + t * GRID;

            int cd[8][8];
#pragma unroll
            for (int i = 0; i < 8; i++)
#pragma unroll
                for (int j = 0; j < 8; j++) cd[i][j] = 0;

#pragma unroll 1
            for (int kt = 0; kt < ND64; kt++) {
                asm volatile("cp.async.wait_group 0;" ::: "memory");  // own chunk g done
                asm volatile("bar.sync 2, 128;" ::: "memory");        // ALL chunk g done

                ld_kt++;
                if (ld_kt == ND64) {
                    ld_kt = 0;
                    ld_tile += GRID;
                    if (ld_tile < TILES_TOT) {
                        lA = (const char*)g_A8 + (size_t)(ld_tile >> 6) * BM * KDIM;
                        lB = (const char*)g_B8 + (size_t)(ld_tile & 63) * BN * KDIM;
                    }
                }
                if (ld_tile < TILES_TOT)
                    load_dp(dbase + (uint32_t)(((g + 1) & 1) * DP_STAGE), lA, lB,
                            KI * BK + ld_kt * 64, dt);
                asm volatile("cp.async.commit_group;" ::: "memory");

                uint32_t sA = dbase + (uint32_t)((g & 1) * DP_STAGE);
                uint32_t sB = sA + 8192;
                uint32_t aB = sA + aBase;

#pragma unroll
                for (int seg = 0; seg < 4; seg++) {
                    uint32_t soff = (uint32_t)(seg << 7);

                    uint32_t a[8][4];
#pragma unroll
                    for (int i = 0; i < 8; i++)
                        lds128(a[i], aB + i * 512 + soff);

#pragma unroll
                    for (int jh = 0; jh < 2; jh++) {
                        uint32_t b[4][4];
#pragma unroll
                        for (int jj = 0; jj < 4; jj++)
                            lds128(b[jj], sB + bOff[jh * 4 + jj] + soff);
#pragma unroll
                        for (int i = 0; i < 8; i++)
#pragma unroll
                            for (int jj = 0; jj < 4; jj++) {
                                int& acc = cd[i][jh * 4 + jj];
                                dp4a_acc(acc, a[i][0], b[jj][0]);
                                dp4a_acc(acc, a[i][1], b[jj][1]);
                                dp4a_acc(acc, a[i][2], b[jj][2]);
                                dp4a_acc(acc, a[i][3], b[jj][3]);
                            }
                    }
                }
                g++;
            }

            // ---- 4-phase merged epilogue (phase k holds rows i = k, k+4) ----
            int n0g = (T & 63) * BN + wn * 32 + tn;
            int m0base = (T >> 6) * BM;
            float scv[8], biv[8];
#pragma unroll
            for (int j = 0; j < 8; j++) {
                scv[j] = g_sc[n0g + 4 * j];
                biv[j] = bias[n0g + 4 * j];
            }
            const int* part = (const int*)(smem + SM_PART);
            int pcol = wn * 32 + tn;

#pragma unroll
            for (int k = 0; k < 4; k++) {
                asm volatile("bar.sync 3, 256;" ::: "memory");   // phase k ready
#pragma unroll
                for (int h = 0; h < 2; h++) {
                    int i = k + 4 * h;
                    int rr = wm * 64 + tm + 8 * i;
                    int pidx = wm * 16 + 8 * h + tm;
                    const int* prw = part + pidx * PART_STRIDE + pcol;
                    float* orow = out + (size_t)(m0base + rr) * NDIM + n0g;
#pragma unroll
                    for (int j = 0; j < 8; j++)
                        orow[4 * j] = (float)(cd[i][j] + prw[4 * j]) * scv[j] + biv[j];
                }
                asm volatile("membar.cta;" ::: "memory");
                asm volatile("bar.arrive 4, 256;" ::: "memory"); // phase k consumed
            }
        }
    }
}

// -------- launch --------
extern "C" void kernel_launch(void* const* d_in, const int* in_sizes, int n_in,
                              void* d_out, int out_size) {
    const float* x        = (const float*)d_in[0];
    const float* in_scale = (const float*)d_in[1];
    const float* act      = (const float*)d_in[2];
    const int*   w        = (const int*)d_in[3];
    const float* w_scale  = (const float*)d_in[4];
    const float* bias     = (const float*)d_in[5];
    float* out = (float*)d_out;

    int M = in_sizes[0] / KDIM;  // 8192

    cudaFuncSetAttribute(gemm_kernel, cudaFuncAttributeMaxDynamicSharedMemorySize, SMEM_TOTAL);

    precomp_scales<<<(KDIM + 255) / 256, 256>>>(in_scale, act, w_scale);

    int xa4 = (M * KDIM) / 4;
    quant_x<<<(xa4 + 255) / 256, 256>>>(x, xa4);

    int wb4 = (NDIM * KDIM) / 4;
    conv_w<<<(wb4 + 255) / 256, 256>>>(w, wb4);

    gemm_kernel<<<GRID, 256, SMEM_TOTAL>>>(bias, out);
}